// round 4
// baseline (speedup 1.0000x reference)
#include <cuda_runtime.h>
#include <stdint.h>

#define TPB 128
#define WARPS_PER_BLK 4
#define NVOX 1000000u
#define RS 68  // smem row stride in floats (conflict-free for LDS.128/STS.128)

typedef unsigned long long u64;

// ---------------- packed f32x2 helpers (Blackwell) ----------------
__device__ __forceinline__ u64 pk2(float lo, float hi) {
    u64 r;
    asm("mov.b64 %0, {%1, %2};" : "=l"(r) : "f"(lo), "f"(hi));
    return r;
}
__device__ __forceinline__ void unpk2(u64 v, float &lo, float &hi) {
    asm("mov.b64 {%0, %1}, %2;" : "=f"(lo), "=f"(hi) : "l"(v));
}
__device__ __forceinline__ u64 fma2(u64 a, u64 b, u64 c) {
    u64 d;
    asm("fma.rn.f32x2 %0, %1, %2, %3;" : "=l"(d) : "l"(a), "l"(b), "l"(c));
    return d;
}

// ------- threefry2x32, key = jax.random.key(42) -> (k1=0, k2=42) ----------
__device__ __forceinline__ void tf2x32(uint32_t x0, uint32_t x1,
                                       uint32_t &o0, uint32_t &o1) {
    const uint32_t ks0 = 0u;
    const uint32_t ks1 = 42u;
    const uint32_t ks2 = 0x1BD11BDAu ^ 0u ^ 42u;
    x0 += ks0; x1 += ks1;
#define TF_R(r) { x0 += x1; x1 = __funnelshift_l(x1, x1, (r)); x1 ^= x0; }
#define TF_G1 TF_R(13) TF_R(15) TF_R(26) TF_R(6)
#define TF_G2 TF_R(17) TF_R(29) TF_R(16) TF_R(24)
    TF_G1 x0 += ks1; x1 += ks2 + 1u;
    TF_G2 x0 += ks2; x1 += ks0 + 2u;
    TF_G1 x0 += ks0; x1 += ks1 + 3u;
    TF_G2 x0 += ks1; x1 += ks2 + 4u;
    TF_G1 x0 += ks2; x1 += ks0 + 5u;
#undef TF_G1
#undef TF_G2
#undef TF_R
    o0 = x0; o1 = x1;
}

// Partitionable threefry bits for flat element index i (i < 2^32):
// counters (hi=0, lo=i); 32-bit output = lane0 ^ lane1.
__device__ __forceinline__ uint32_t tf_bits_partitionable(uint32_t i) {
    uint32_t o0, o1;
    tf2x32(0u, i, o0, o1);
    return o0 ^ o1;
}

// bits -> jax.random.normal sample * 1e-6 (SYMEIG_EPS), XLA ErfInv32 exact
__device__ __forceinline__ float noise_from_bits(uint32_t bits) {
    const float LO = -0.99999994f;  // nextafter(-1,0); (1-LO) rounds to 2.0f
    float f = __uint_as_float((bits >> 9) | 0x3f800000u) - 1.0f;  // [0,1)
    float u = fmaxf(LO, fmaf(f, 2.0f, LO));
    float z = 1.0f - u * u;  // Sterbenz-exact where log1p accuracy matters
    float w = -0.6931471805599453f * __log2f(z);
    // small branch (w < 5)
    float ws = w - 2.5f;
    float p1 = fmaf(2.81022636e-08f, ws, 3.43273939e-07f);
    p1 = fmaf(p1, ws, -3.5233877e-06f);
    p1 = fmaf(p1, ws, -4.39150654e-06f);
    p1 = fmaf(p1, ws, 0.00021858087f);
    p1 = fmaf(p1, ws, -0.00125372503f);
    p1 = fmaf(p1, ws, -0.00417768164f);
    p1 = fmaf(p1, ws, 0.246640727f);
    p1 = fmaf(p1, ws, 1.50140941f);
    // big branch (w >= 5)
    float wb = __fsqrt_rn(w) - 3.0f;
    float p2 = fmaf(-0.000200214257f, wb, 0.000100950558f);
    p2 = fmaf(p2, wb, 0.00134934322f);
    p2 = fmaf(p2, wb, -0.00367342844f);
    p2 = fmaf(p2, wb, 0.00573950773f);
    p2 = fmaf(p2, wb, -0.0076224613f);
    p2 = fmaf(p2, wb, 0.00943887047f);
    p2 = fmaf(p2, wb, 1.00167406f);
    p2 = fmaf(p2, wb, 2.83297682f);
    float p = (w < 5.0f) ? p1 : p2;
    return 1.0e-6f * (1.41421353816986084f * (p * u));
}

// ---------------- FA from symmetric 3x3, cancellation-free -----------------
__device__ __forceinline__ float fa_voxel(const float *fit, const float *n,
                                          float mind) {
    float a00 = fit[0] + n[0];
    float a11 = fit[2] + n[4];
    float a22 = fit[5] + n[8];
    float a01 = 0.5f * ((fit[1] + n[1]) + (fit[1] + n[3]));
    float a02 = 0.5f * ((fit[3] + n[2]) + (fit[3] + n[6]));
    float a12 = 0.5f * ((fit[4] + n[5]) + (fit[4] + n[7]));

    float q = (a00 + a11 + a22) * (1.0f / 3.0f);
    float m0 = a00 - q, m1 = a11 - q, m2 = a22 - q;
    float off = fmaf(a01, a01, fmaf(a02, a02, a12 * a12));
    float S = fmaf(m0, m0, fmaf(m1, m1, fmaf(m2, m2, 2.0f * off)));
    // unclamped FA: num = 1.5*S, den = S + 3*q^2 (no eigenvalues needed)
    float fa_fast = __fsqrt_rn(__fdividef(1.5f * S, fmaf(3.0f * q, q, S)));
    float p = __fsqrt_rn(S * (1.0f / 6.0f));
    if (q - 2.0f * p >= mind) return fa_fast;  // lambda_min >= q-2p always

    float det = m0 * fmaf(m1, m2, -a12 * a12)
              - a01 * fmaf(a01, m2, -a12 * a02)
              + a02 * fmaf(a01, a12, -m1 * a02);
    float pinv = __fdividef(1.0f, p);
    float r = 0.5f * det * pinv * pinv * pinv;
    r = fminf(fmaxf(r, -1.0f), 1.0f);  // NaN (p==0) collapses to -1
    float phi = acosf(r) * (1.0f / 3.0f);
    float l3 = fmaf(2.0f * p, __cosf(phi + 2.0943951023931953f), q);  // min
    if (l3 >= mind) return fa_fast;

    float l1 = fmaf(2.0f * p, __cosf(phi), q);  // max
    float l2 = 3.0f * q - l1 - l3;
    l1 = fmaxf(l1, mind);
    l2 = fmaxf(l2, mind);
    l3 = fmaxf(l3, mind);
    float d12 = l1 - l2, d23 = l2 - l3, d31 = l3 - l1;
    float num = 0.5f * fmaf(d12, d12, fmaf(d23, d23, d31 * d31));
    float den = fmaf(l1, l1, fmaf(l2, l2, l3 * l3));
    return __fsqrt_rn(__fdividef(num, den));
}

// ---------------- main kernel ----------------------------------------------
__global__ void __launch_bounds__(TPB)
fa_kernel(const float *__restrict__ dwi, const float *__restrict__ mask,
          const float *__restrict__ Winv, const float *__restrict__ mindp,
          float *__restrict__ out) {
    __shared__ __align__(16) float Wsh[384];
    __shared__ __align__(16) float tile[WARPS_PER_BLK][32 * RS];

    // stage rows 0..5 of design_matrix_inv, pre-scaled by ln2 (we feed lg2)
    for (int k = threadIdx.x; k < 384; k += TPB)
        Wsh[k] = Winv[k] * 0.6931471805599453f;

    const int warp = threadIdx.x >> 5;
    const int lane = threadIdx.x & 31;
    const unsigned vw = (blockIdx.x * WARPS_PER_BLK + warp) * 32u;  // base voxel

    // coalesced load of this warp's 32 voxels (8 KB) into padded smem rows
    const float4 *__restrict__ dwi4 = reinterpret_cast<const float4 *>(dwi);
    float *trow = &tile[warp][0];
#pragma unroll
    for (int k = 0; k < 16; ++k) {
        unsigned fidx = vw * 16u + (unsigned)(k * 32 + lane);  // global float4 idx
        if (fidx < NVOX * 16u) {
            float4 val = dwi4[fidx];
            unsigned local = (unsigned)(k * 32 + lane);  // 0..511
            unsigned vox = local >> 4, elem = local & 15u;
            *reinterpret_cast<float4 *>(&trow[vox * RS + elem * 4]) = val;
        }
    }
    __syncthreads();  // covers Wsh and tile

    const unsigned v = vw + (unsigned)lane;
    if (v >= NVOX) return;

    const float mind = __ldg(mindp);
    const float *myrow = &trow[lane * RS];

    u64 acc[6];
#pragma unroll
    for (int i = 0; i < 6; ++i) acc[i] = 0ull;

#pragma unroll 4
    for (int jt = 0; jt < 16; ++jt) {
        float4 a = *reinterpret_cast<const float4 *>(&myrow[jt * 4]);
        float l0 = __log2f(fmaxf(a.x, mind));
        float l1 = __log2f(fmaxf(a.y, mind));
        float l2 = __log2f(fmaxf(a.z, mind));
        float l3 = __log2f(fmaxf(a.w, mind));
        u64 l01 = pk2(l0, l1), l23 = pk2(l2, l3);
#pragma unroll
        for (int i = 0; i < 6; ++i) {
            ulonglong2 w =
                *reinterpret_cast<const ulonglong2 *>(&Wsh[i * 64 + jt * 4]);
            acc[i] = fma2(w.x, l01, acc[i]);
            acc[i] = fma2(w.y, l23, acc[i]);
        }
    }

    float fit[6];
#pragma unroll
    for (int i = 0; i < 6; ++i) {
        float x, y;
        unpk2(acc[i], x, y);
        fit[i] = x + y;
    }

    // partitionable-threefry noise: element flat index = 9v + j
    float nn[9];
    uint32_t base = 9u * v;
#pragma unroll 3
    for (int j = 0; j < 9; ++j)
        nn[j] = noise_from_bits(tf_bits_partitionable(base + (uint32_t)j));

    out[v] = fa_voxel(fit, nn, mind) * __ldg(mask + v);
}

extern "C" void kernel_launch(void *const *d_in, const int *in_sizes, int n_in,
                              void *d_out, int out_size) {
    const float *dwi  = (const float *)d_in[0];   // [100,100,100,64]
    const float *mask = (const float *)d_in[1];   // [100,100,100,1]
    const float *winv = (const float *)d_in[2];   // [7,64]
    const float *mind = (const float *)d_in[3];   // scalar
    float *out = (float *)d_out;                  // [100,100,100,1]
    (void)in_sizes; (void)n_in; (void)out_size;

    unsigned vox_per_blk = TPB;  // 1 voxel per thread
    dim3 grid((NVOX + vox_per_blk - 1) / vox_per_blk);
    fa_kernel<<<grid, TPB>>>(dwi, mask, winv, mind, out);
}

// round 5
// speedup vs baseline: 1.0495x; 1.0495x over previous
#include <cuda_runtime.h>
#include <stdint.h>

#define TPB 128
#define WARPS_PER_BLK 4
#define NVOX 1000000u
#define RS 36  // smem row stride (floats): 144B ≡ 16 mod 128 -> conflict-free

typedef unsigned long long u64;

// ---------------- packed f32x2 helpers (Blackwell) ----------------
__device__ __forceinline__ u64 pk2(float lo, float hi) {
    u64 r;
    asm("mov.b64 %0, {%1, %2};" : "=l"(r) : "f"(lo), "f"(hi));
    return r;
}
__device__ __forceinline__ void unpk2(u64 v, float &lo, float &hi) {
    asm("mov.b64 {%0, %1}, %2;" : "=f"(lo), "=f"(hi) : "l"(v));
}
__device__ __forceinline__ u64 fma2(u64 a, u64 b, u64 c) {
    u64 d;
    asm("fma.rn.f32x2 %0, %1, %2, %3;" : "=l"(d) : "l"(a), "l"(b), "l"(c));
    return d;
}

// ------- threefry2x32, key = jax.random.key(42) -> (k1=0, k2=42) ----------
__device__ __forceinline__ void tf2x32(uint32_t x0, uint32_t x1,
                                       uint32_t &o0, uint32_t &o1) {
    const uint32_t ks0 = 0u;
    const uint32_t ks1 = 42u;
    const uint32_t ks2 = 0x1BD11BDAu ^ 0u ^ 42u;
    x0 += ks0; x1 += ks1;
#define TF_R(r) { x0 += x1; x1 = __funnelshift_l(x1, x1, (r)); x1 ^= x0; }
#define TF_G1 TF_R(13) TF_R(15) TF_R(26) TF_R(6)
#define TF_G2 TF_R(17) TF_R(29) TF_R(16) TF_R(24)
    TF_G1 x0 += ks1; x1 += ks2 + 1u;
    TF_G2 x0 += ks2; x1 += ks0 + 2u;
    TF_G1 x0 += ks0; x1 += ks1 + 3u;
    TF_G2 x0 += ks1; x1 += ks2 + 4u;
    TF_G1 x0 += ks2; x1 += ks0 + 5u;
#undef TF_G1
#undef TF_G2
#undef TF_R
    o0 = x0; o1 = x1;
}

// Partitionable threefry: counters (hi=0, lo=i); 32-bit output = lane0 ^ lane1.
__device__ __forceinline__ uint32_t tf_bits_partitionable(uint32_t i) {
    uint32_t o0, o1;
    tf2x32(0u, i, o0, o1);
    return o0 ^ o1;
}

// bits -> jax.random.normal sample * 1e-6 (SYMEIG_EPS), XLA ErfInv32 exact
__device__ __forceinline__ float noise_from_bits(uint32_t bits) {
    const float LO = -0.99999994f;  // nextafter(-1,0); (1-LO) rounds to 2.0f
    float f = __uint_as_float((bits >> 9) | 0x3f800000u) - 1.0f;  // [0,1)
    float u = fmaxf(LO, fmaf(f, 2.0f, LO));
    float z = 1.0f - u * u;  // Sterbenz-exact where log1p accuracy matters
    float w = -0.6931471805599453f * __log2f(z);
    // small branch (w < 5)
    float ws = w - 2.5f;
    float p1 = fmaf(2.81022636e-08f, ws, 3.43273939e-07f);
    p1 = fmaf(p1, ws, -3.5233877e-06f);
    p1 = fmaf(p1, ws, -4.39150654e-06f);
    p1 = fmaf(p1, ws, 0.00021858087f);
    p1 = fmaf(p1, ws, -0.00125372503f);
    p1 = fmaf(p1, ws, -0.00417768164f);
    p1 = fmaf(p1, ws, 0.246640727f);
    p1 = fmaf(p1, ws, 1.50140941f);
    // big branch (w >= 5)
    float wb = __fsqrt_rn(w) - 3.0f;
    float p2 = fmaf(-0.000200214257f, wb, 0.000100950558f);
    p2 = fmaf(p2, wb, 0.00134934322f);
    p2 = fmaf(p2, wb, -0.00367342844f);
    p2 = fmaf(p2, wb, 0.00573950773f);
    p2 = fmaf(p2, wb, -0.0076224613f);
    p2 = fmaf(p2, wb, 0.00943887047f);
    p2 = fmaf(p2, wb, 1.00167406f);
    p2 = fmaf(p2, wb, 2.83297682f);
    float p = (w < 5.0f) ? p1 : p2;
    return 1.0e-6f * (1.41421353816986084f * (p * u));
}

// ---------------- FA from symmetric 3x3, cancellation-free -----------------
__device__ __forceinline__ float fa_voxel(const float *fit, const float *n,
                                          float mind) {
    float a00 = fit[0] + n[0];
    float a11 = fit[2] + n[4];
    float a22 = fit[5] + n[8];
    float a01 = 0.5f * ((fit[1] + n[1]) + (fit[1] + n[3]));
    float a02 = 0.5f * ((fit[3] + n[2]) + (fit[3] + n[6]));
    float a12 = 0.5f * ((fit[4] + n[5]) + (fit[4] + n[7]));

    float q = (a00 + a11 + a22) * (1.0f / 3.0f);
    float m0 = a00 - q, m1 = a11 - q, m2 = a22 - q;
    float off = fmaf(a01, a01, fmaf(a02, a02, a12 * a12));
    float S = fmaf(m0, m0, fmaf(m1, m1, fmaf(m2, m2, 2.0f * off)));
    // unclamped FA: num = 1.5*S, den = S + 3*q^2 (no eigenvalues needed)
    float fa_fast = __fsqrt_rn(__fdividef(1.5f * S, fmaf(3.0f * q, q, S)));
    float p = __fsqrt_rn(S * (1.0f / 6.0f));
    if (q - 2.0f * p >= mind) return fa_fast;  // lambda_min >= q-2p always

    float det = m0 * fmaf(m1, m2, -a12 * a12)
              - a01 * fmaf(a01, m2, -a12 * a02)
              + a02 * fmaf(a01, a12, -m1 * a02);
    float pinv = __fdividef(1.0f, p);
    float r = 0.5f * det * pinv * pinv * pinv;
    r = fminf(fmaxf(r, -1.0f), 1.0f);  // NaN (p==0) collapses to -1
    float phi = acosf(r) * (1.0f / 3.0f);
    float l3 = fmaf(2.0f * p, __cosf(phi + 2.0943951023931953f), q);  // min
    if (l3 >= mind) return fa_fast;

    float l1 = fmaf(2.0f * p, __cosf(phi), q);  // max
    float l2 = 3.0f * q - l1 - l3;
    l1 = fmaxf(l1, mind);
    l2 = fmaxf(l2, mind);
    l3 = fmaxf(l3, mind);
    float d12 = l1 - l2, d23 = l2 - l3, d31 = l3 - l1;
    float num = 0.5f * fmaf(d12, d12, fmaf(d23, d23, d31 * d31));
    float den = fmaf(l1, l1, fmaf(l2, l2, l3 * l3));
    return __fsqrt_rn(__fdividef(num, den));
}

// ---------------- main kernel ----------------------------------------------
__global__ void __launch_bounds__(TPB)
fa_kernel(const float *__restrict__ dwi, const float *__restrict__ mask,
          const float *__restrict__ Winv, const float *__restrict__ mindp,
          float *__restrict__ out) {
    __shared__ __align__(16) float Wsh[384];
    __shared__ __align__(16) float tile[WARPS_PER_BLK][32 * RS];

    // stage rows 0..5 of design_matrix_inv, pre-scaled by ln2 (we feed lg2)
    for (int k = threadIdx.x; k < 384; k += TPB)
        Wsh[k] = Winv[k] * 0.6931471805599453f;
    __syncthreads();  // only needed for Wsh; tile is warp-private below

    const int warp = threadIdx.x >> 5;
    const int lane = threadIdx.x & 31;
    const unsigned vw = (blockIdx.x * WARPS_PER_BLK + warp) * 32u;  // base voxel
    const unsigned v = vw + (unsigned)lane;
    const bool live = (v < NVOX);

    const float mind = __ldg(mindp);
    const float4 *__restrict__ dwi4 = reinterpret_cast<const float4 *>(dwi);
    float *trow = &tile[warp][0];

    // phase-p loads: 8-lane group g = lane>>3 reads voxel (k*4+g)'s
    // float4 chunk (p*8 + (lane&7)) -> 128B contiguous per group.
    const unsigned g = lane >> 3u, e = lane & 7u;

    // ---- load phase 0 (elems 0..31 of all 32 voxels) ----
    float4 r0[8];
#pragma unroll
    for (int k = 0; k < 8; ++k) {
        unsigned gv = vw + k * 4u + g;
        r0[k] = (gv < NVOX) ? dwi4[(size_t)gv * 16u + e]
                            : make_float4(1.f, 1.f, 1.f, 1.f);
    }
#pragma unroll
    for (int k = 0; k < 8; ++k)
        *reinterpret_cast<float4 *>(&trow[(k * 4u + g) * RS + e * 4u]) = r0[k];
    __syncwarp();

    // ---- prefetch phase 1 (elems 32..63) into registers ----
    float4 r1[8];
#pragma unroll
    for (int k = 0; k < 8; ++k) {
        unsigned gv = vw + k * 4u + g;
        r1[k] = (gv < NVOX) ? dwi4[(size_t)gv * 16u + 8u + e]
                            : make_float4(1.f, 1.f, 1.f, 1.f);
    }

    // ---- independent ALU work: threefry noise (hides load latency) ----
    float nn[9];
    {
        uint32_t base = 9u * v;
#pragma unroll 3
        for (int j = 0; j < 9; ++j)
            nn[j] = noise_from_bits(tf_bits_partitionable(base + (uint32_t)j));
    }

    u64 acc[6];
#pragma unroll
    for (int i = 0; i < 6; ++i) acc[i] = 0ull;

    const float *myrow = &trow[lane * RS];

    // ---- consume phase 0 ----
#pragma unroll
    for (int jt = 0; jt < 8; ++jt) {
        float4 a = *reinterpret_cast<const float4 *>(&myrow[jt * 4]);
        float l0 = __log2f(fmaxf(a.x, mind));
        float l1 = __log2f(fmaxf(a.y, mind));
        float l2 = __log2f(fmaxf(a.z, mind));
        float l3 = __log2f(fmaxf(a.w, mind));
        u64 l01 = pk2(l0, l1), l23 = pk2(l2, l3);
#pragma unroll
        for (int i = 0; i < 6; ++i) {
            ulonglong2 w =
                *reinterpret_cast<const ulonglong2 *>(&Wsh[i * 64 + jt * 4]);
            acc[i] = fma2(w.x, l01, acc[i]);
            acc[i] = fma2(w.y, l23, acc[i]);
        }
    }
    __syncwarp();

    // ---- store + consume phase 1 ----
#pragma unroll
    for (int k = 0; k < 8; ++k)
        *reinterpret_cast<float4 *>(&trow[(k * 4u + g) * RS + e * 4u]) = r1[k];
    __syncwarp();

#pragma unroll
    for (int jt = 0; jt < 8; ++jt) {
        float4 a = *reinterpret_cast<const float4 *>(&myrow[jt * 4]);
        float l0 = __log2f(fmaxf(a.x, mind));
        float l1 = __log2f(fmaxf(a.y, mind));
        float l2 = __log2f(fmaxf(a.z, mind));
        float l3 = __log2f(fmaxf(a.w, mind));
        u64 l01 = pk2(l0, l1), l23 = pk2(l2, l3);
#pragma unroll
        for (int i = 0; i < 6; ++i) {
            ulonglong2 w = *reinterpret_cast<const ulonglong2 *>(
                &Wsh[i * 64 + 32 + jt * 4]);
            acc[i] = fma2(w.x, l01, acc[i]);
            acc[i] = fma2(w.y, l23, acc[i]);
        }
    }

    float fit[6];
#pragma unroll
    for (int i = 0; i < 6; ++i) {
        float x, y;
        unpk2(acc[i], x, y);
        fit[i] = x + y;
    }

    if (live)
        out[v] = fa_voxel(fit, nn, mind) * __ldg(mask + v);
}

extern "C" void kernel_launch(void *const *d_in, const int *in_sizes, int n_in,
                              void *d_out, int out_size) {
    const float *dwi  = (const float *)d_in[0];   // [100,100,100,64]
    const float *mask = (const float *)d_in[1];   // [100,100,100,1]
    const float *winv = (const float *)d_in[2];   // [7,64]
    const float *mind = (const float *)d_in[3];   // scalar
    float *out = (float *)d_out;                  // [100,100,100,1]
    (void)in_sizes; (void)n_in; (void)out_size;

    dim3 grid((NVOX + TPB - 1) / TPB);
    fa_kernel<<<grid, TPB>>>(dwi, mask, winv, mind, out);
}

// round 6
// speedup vs baseline: 1.2355x; 1.1772x over previous
#include <cuda_runtime.h>
#include <stdint.h>

#define TPB 128
#define WARPS_PER_BLK 4
#define NVOX 1000000u
#define RS 36  // smem row stride (floats): 144B; conflict-free phases

typedef unsigned long long u64;

// ---------------- packed f32x2 helpers (Blackwell) ----------------
__device__ __forceinline__ u64 pk2(float lo, float hi) {
    u64 r;
    asm("mov.b64 %0, {%1, %2};" : "=l"(r) : "f"(lo), "f"(hi));
    return r;
}
__device__ __forceinline__ void unpk2(u64 v, float &lo, float &hi) {
    asm("mov.b64 {%0, %1}, %2;" : "=f"(lo), "=f"(hi) : "l"(v));
}
__device__ __forceinline__ u64 fma2(u64 a, u64 b, u64 c) {
    u64 d;
    asm("fma.rn.f32x2 %0, %1, %2, %3;" : "=l"(d) : "l"(a), "l"(b), "l"(c));
    return d;
}

// ---------------- cp.async 16B ----------------
__device__ __forceinline__ void cp_async16(uint32_t saddr, const void *gptr) {
    asm volatile("cp.async.ca.shared.global [%0], [%1], 16;"
                 :: "r"(saddr), "l"(gptr) : "memory");
}
__device__ __forceinline__ void cp_commit() {
    asm volatile("cp.async.commit_group;" ::: "memory");
}
__device__ __forceinline__ void cp_wait0() {
    asm volatile("cp.async.wait_group 0;" ::: "memory");
}

// ------- threefry2x32, key = jax.random.key(42) -> (k1=0, k2=42) ----------
__device__ __forceinline__ void tf2x32(uint32_t x0, uint32_t x1,
                                       uint32_t &o0, uint32_t &o1) {
    const uint32_t ks0 = 0u;
    const uint32_t ks1 = 42u;
    const uint32_t ks2 = 0x1BD11BDAu ^ 0u ^ 42u;
    x0 += ks0; x1 += ks1;
#define TF_R(r) { x0 += x1; x1 = __funnelshift_l(x1, x1, (r)); x1 ^= x0; }
#define TF_G1 TF_R(13) TF_R(15) TF_R(26) TF_R(6)
#define TF_G2 TF_R(17) TF_R(29) TF_R(16) TF_R(24)
    TF_G1 x0 += ks1; x1 += ks2 + 1u;
    TF_G2 x0 += ks2; x1 += ks0 + 2u;
    TF_G1 x0 += ks0; x1 += ks1 + 3u;
    TF_G2 x0 += ks1; x1 += ks2 + 4u;
    TF_G1 x0 += ks2; x1 += ks0 + 5u;
#undef TF_G1
#undef TF_G2
#undef TF_R
    o0 = x0; o1 = x1;
}

// Partitionable threefry: counters (hi=0, lo=i); 32-bit output = lane0 ^ lane1.
__device__ __forceinline__ uint32_t tf_bits_partitionable(uint32_t i) {
    uint32_t o0, o1;
    tf2x32(0u, i, o0, o1);
    return o0 ^ o1;
}

// bits -> jax.random.normal sample * 1e-6 (SYMEIG_EPS), XLA ErfInv32 exact
__device__ __forceinline__ float noise_from_bits(uint32_t bits) {
    const float LO = -0.99999994f;  // nextafter(-1,0); (1-LO) rounds to 2.0f
    float f = __uint_as_float((bits >> 9) | 0x3f800000u) - 1.0f;  // [0,1)
    float u = fmaxf(LO, fmaf(f, 2.0f, LO));
    float z = 1.0f - u * u;  // Sterbenz-exact where log1p accuracy matters
    float w = -0.6931471805599453f * __log2f(z);
    float ws = w - 2.5f;
    float p1 = fmaf(2.81022636e-08f, ws, 3.43273939e-07f);
    p1 = fmaf(p1, ws, -3.5233877e-06f);
    p1 = fmaf(p1, ws, -4.39150654e-06f);
    p1 = fmaf(p1, ws, 0.00021858087f);
    p1 = fmaf(p1, ws, -0.00125372503f);
    p1 = fmaf(p1, ws, -0.00417768164f);
    p1 = fmaf(p1, ws, 0.246640727f);
    p1 = fmaf(p1, ws, 1.50140941f);
    float wb = __fsqrt_rn(w) - 3.0f;
    float p2 = fmaf(-0.000200214257f, wb, 0.000100950558f);
    p2 = fmaf(p2, wb, 0.00134934322f);
    p2 = fmaf(p2, wb, -0.00367342844f);
    p2 = fmaf(p2, wb, 0.00573950773f);
    p2 = fmaf(p2, wb, -0.0076224613f);
    p2 = fmaf(p2, wb, 0.00943887047f);
    p2 = fmaf(p2, wb, 1.00167406f);
    p2 = fmaf(p2, wb, 2.83297682f);
    float p = (w < 5.0f) ? p1 : p2;
    return 1.0e-6f * (1.41421353816986084f * (p * u));
}

// ---------------- FA from symmetric 3x3, cancellation-free -----------------
__device__ __forceinline__ float fa_voxel(const float *fit, const float *n,
                                          float mind) {
    float a00 = fit[0] + n[0];
    float a11 = fit[2] + n[4];
    float a22 = fit[5] + n[8];
    float a01 = 0.5f * ((fit[1] + n[1]) + (fit[1] + n[3]));
    float a02 = 0.5f * ((fit[3] + n[2]) + (fit[3] + n[6]));
    float a12 = 0.5f * ((fit[4] + n[5]) + (fit[4] + n[7]));

    float q = (a00 + a11 + a22) * (1.0f / 3.0f);
    float m0 = a00 - q, m1 = a11 - q, m2 = a22 - q;
    float off = fmaf(a01, a01, fmaf(a02, a02, a12 * a12));
    float S = fmaf(m0, m0, fmaf(m1, m1, fmaf(m2, m2, 2.0f * off)));
    float fa_fast = __fsqrt_rn(__fdividef(1.5f * S, fmaf(3.0f * q, q, S)));
    float p = __fsqrt_rn(S * (1.0f / 6.0f));
    if (q - 2.0f * p >= mind) return fa_fast;  // lambda_min >= q-2p always

    float det = m0 * fmaf(m1, m2, -a12 * a12)
              - a01 * fmaf(a01, m2, -a12 * a02)
              + a02 * fmaf(a01, a12, -m1 * a02);
    float pinv = __fdividef(1.0f, p);
    float r = 0.5f * det * pinv * pinv * pinv;
    r = fminf(fmaxf(r, -1.0f), 1.0f);  // NaN (p==0) collapses to -1
    float phi = acosf(r) * (1.0f / 3.0f);
    float l3 = fmaf(2.0f * p, __cosf(phi + 2.0943951023931953f), q);  // min
    if (l3 >= mind) return fa_fast;

    float l1 = fmaf(2.0f * p, __cosf(phi), q);  // max
    float l2 = 3.0f * q - l1 - l3;
    l1 = fmaxf(l1, mind);
    l2 = fmaxf(l2, mind);
    l3 = fmaxf(l3, mind);
    float d12 = l1 - l2, d23 = l2 - l3, d31 = l3 - l1;
    float num = 0.5f * fmaf(d12, d12, fmaf(d23, d23, d31 * d31));
    float den = fmaf(l1, l1, fmaf(l2, l2, l3 * l3));
    return __fsqrt_rn(__fdividef(num, den));
}

// ---------------- main kernel ----------------------------------------------
__global__ void __launch_bounds__(TPB, 8)
fa_kernel(const float *__restrict__ dwi, const float *__restrict__ mask,
          const float *__restrict__ Winv, const float *__restrict__ mindp,
          float *__restrict__ out) {
    __shared__ __align__(16) float Wsh[384];
    __shared__ __align__(16) float tile[WARPS_PER_BLK][32 * RS];

    for (int k = threadIdx.x; k < 384; k += TPB)
        Wsh[k] = Winv[k] * 0.6931471805599453f;
    __syncthreads();  // Wsh only; tile is warp-private

    const int warp = threadIdx.x >> 5;
    const int lane = threadIdx.x & 31;
    const unsigned vw = (blockIdx.x * WARPS_PER_BLK + warp) * 32u;
    const unsigned v = vw + (unsigned)lane;
    const bool live = (v < NVOX);

    const float mind = __ldg(mindp);
    const float4 *__restrict__ dwi4 = reinterpret_cast<const float4 *>(dwi);
    float *trow = &tile[warp][0];
    const uint32_t trow_sa =
        (uint32_t)__cvta_generic_to_shared(&tile[warp][0]);

    const unsigned g = lane >> 3u, e = lane & 7u;

    // ---- async-load phase 0 (elems 0..31 of the warp's 32 voxels) ----
#pragma unroll
    for (int k = 0; k < 8; ++k) {
        unsigned gv = min(vw + (unsigned)(k * 4) + g, NVOX - 1u);
        cp_async16(trow_sa + (unsigned)(k * 4 + g) * (RS * 4u) + e * 16u,
                   dwi4 + (size_t)gv * 16u + e);
    }
    cp_commit();

    // ---- pure-ALU threefry bits (hides phase-0 load latency) ----
    uint32_t bits[9];
    {
        uint32_t base = 9u * v;
#pragma unroll
        for (int j = 0; j < 9; ++j)
            bits[j] = tf_bits_partitionable(base + (uint32_t)j);
    }

    cp_wait0();
    __syncwarp();

    // ---- consume phase 0 ----
    u64 acc[6];
#pragma unroll
    for (int i = 0; i < 6; ++i) acc[i] = 0ull;
    const float *myrow = &trow[lane * RS];
#pragma unroll
    for (int jt = 0; jt < 8; ++jt) {
        float4 a = *reinterpret_cast<const float4 *>(&myrow[jt * 4]);
        float l0 = __log2f(fmaxf(a.x, mind));
        float l1 = __log2f(fmaxf(a.y, mind));
        float l2 = __log2f(fmaxf(a.z, mind));
        float l3 = __log2f(fmaxf(a.w, mind));
        u64 l01 = pk2(l0, l1), l23 = pk2(l2, l3);
#pragma unroll
        for (int i = 0; i < 6; ++i) {
            ulonglong2 w =
                *reinterpret_cast<const ulonglong2 *>(&Wsh[i * 64 + jt * 4]);
            acc[i] = fma2(w.x, l01, acc[i]);
            acc[i] = fma2(w.y, l23, acc[i]);
        }
    }
    __syncwarp();  // whole warp done reading phase 0

    // ---- async-load phase 1 into same tile (WAR-safe: LDS long done) ----
#pragma unroll
    for (int k = 0; k < 8; ++k) {
        unsigned gv = min(vw + (unsigned)(k * 4) + g, NVOX - 1u);
        cp_async16(trow_sa + (unsigned)(k * 4 + g) * (RS * 4u) + e * 16u,
                   dwi4 + (size_t)gv * 16u + 8u + e);
    }
    cp_commit();

    // ---- bits -> noise (FMA/MUFU work hides phase-1 load latency) ----
    float nn[9];
#pragma unroll
    for (int j = 0; j < 9; ++j) nn[j] = noise_from_bits(bits[j]);

    cp_wait0();
    __syncwarp();

    // ---- consume phase 1 ----
#pragma unroll
    for (int jt = 0; jt < 8; ++jt) {
        float4 a = *reinterpret_cast<const float4 *>(&myrow[jt * 4]);
        float l0 = __log2f(fmaxf(a.x, mind));
        float l1 = __log2f(fmaxf(a.y, mind));
        float l2 = __log2f(fmaxf(a.z, mind));
        float l3 = __log2f(fmaxf(a.w, mind));
        u64 l01 = pk2(l0, l1), l23 = pk2(l2, l3);
#pragma unroll
        for (int i = 0; i < 6; ++i) {
            ulonglong2 w = *reinterpret_cast<const ulonglong2 *>(
                &Wsh[i * 64 + 32 + jt * 4]);
            acc[i] = fma2(w.x, l01, acc[i]);
            acc[i] = fma2(w.y, l23, acc[i]);
        }
    }

    float fit[6];
#pragma unroll
    for (int i = 0; i < 6; ++i) {
        float x, y;
        unpk2(acc[i], x, y);
        fit[i] = x + y;
    }

    if (live)
        out[v] = fa_voxel(fit, nn, mind) * __ldg(mask + v);
}

extern "C" void kernel_launch(void *const *d_in, const int *in_sizes, int n_in,
                              void *d_out, int out_size) {
    const float *dwi  = (const float *)d_in[0];   // [100,100,100,64]
    const float *mask = (const float *)d_in[1];   // [100,100,100,1]
    const float *winv = (const float *)d_in[2];   // [7,64]
    const float *mind = (const float *)d_in[3];   // scalar
    float *out = (float *)d_out;                  // [100,100,100,1]
    (void)in_sizes; (void)n_in; (void)out_size;

    dim3 grid((NVOX + TPB - 1) / TPB);
    fa_kernel<<<grid, TPB>>>(dwi, mask, winv, mind, out);
}

// round 7
// speedup vs baseline: 1.2395x; 1.0032x over previous
#include <cuda_runtime.h>
#include <stdint.h>

#define TPB 128
#define WARPS_PER_BLK 4
#define NVOX 1000000u
#define RS 36  // smem row stride (floats): conflict-free for both phases

typedef unsigned long long u64;

// ---------------- packed f32x2 helpers (Blackwell) ----------------
__device__ __forceinline__ u64 pk2(float lo, float hi) {
    u64 r;
    asm("mov.b64 %0, {%1, %2};" : "=l"(r) : "f"(lo), "f"(hi));
    return r;
}
__device__ __forceinline__ void unpk2(u64 v, float &lo, float &hi) {
    asm("mov.b64 {%0, %1}, %2;" : "=f"(lo), "=f"(hi) : "l"(v));
}
__device__ __forceinline__ u64 fma2(u64 a, u64 b, u64 c) {
    u64 d;
    asm("fma.rn.f32x2 %0, %1, %2, %3;" : "=l"(d) : "l"(a), "l"(b), "l"(c));
    return d;
}

// ---------------- cp.async 16B ----------------
__device__ __forceinline__ void cp_async16(uint32_t saddr, const void *gptr) {
    asm volatile("cp.async.ca.shared.global [%0], [%1], 16;"
                 :: "r"(saddr), "l"(gptr) : "memory");
}
__device__ __forceinline__ void cp_commit() {
    asm volatile("cp.async.commit_group;" ::: "memory");
}
__device__ __forceinline__ void cp_wait0() {
    asm volatile("cp.async.wait_group 0;" ::: "memory");
}

// ------- threefry2x32, key = jax.random.key(42) -> (k1=0, k2=42) ----------
__device__ __forceinline__ uint32_t tf_bits_partitionable(uint32_t i) {
    uint32_t x0 = 0u, x1 = i;
    const uint32_t ks0 = 0u;
    const uint32_t ks1 = 42u;
    const uint32_t ks2 = 0x1BD11BDAu ^ 0u ^ 42u;
    x0 += ks0; x1 += ks1;
#define TF_R(r) { x0 += x1; x1 = __funnelshift_l(x1, x1, (r)); x1 ^= x0; }
#define TF_G1 TF_R(13) TF_R(15) TF_R(26) TF_R(6)
#define TF_G2 TF_R(17) TF_R(29) TF_R(16) TF_R(24)
    TF_G1 x0 += ks1; x1 += ks2 + 1u;
    TF_G2 x0 += ks2; x1 += ks0 + 2u;
    TF_G1 x0 += ks0; x1 += ks1 + 3u;
    TF_G2 x0 += ks1; x1 += ks2 + 4u;
    TF_G1 x0 += ks2; x1 += ks0 + 5u;
#undef TF_G1
#undef TF_G2
#undef TF_R
    return x0 ^ x1;  // partitionable path: lane0 ^ lane1
}

// bits -> jax.random.normal sample * 1e-6 (SYMEIG_EPS), XLA ErfInv32 exact
__device__ __forceinline__ float noise_from_bits(uint32_t bits) {
    const float LO = -0.99999994f;  // nextafter(-1,0); (1-LO) rounds to 2.0f
    float f = __uint_as_float((bits >> 9) | 0x3f800000u) - 1.0f;  // [0,1)
    float u = fmaxf(LO, fmaf(f, 2.0f, LO));
    float z = 1.0f - u * u;  // Sterbenz-exact where log1p accuracy matters
    float w = -0.6931471805599453f * __log2f(z);
    float ws = w - 2.5f;
    float p1 = fmaf(2.81022636e-08f, ws, 3.43273939e-07f);
    p1 = fmaf(p1, ws, -3.5233877e-06f);
    p1 = fmaf(p1, ws, -4.39150654e-06f);
    p1 = fmaf(p1, ws, 0.00021858087f);
    p1 = fmaf(p1, ws, -0.00125372503f);
    p1 = fmaf(p1, ws, -0.00417768164f);
    p1 = fmaf(p1, ws, 0.246640727f);
    p1 = fmaf(p1, ws, 1.50140941f);
    float wb = __fsqrt_rn(w) - 3.0f;
    float p2 = fmaf(-0.000200214257f, wb, 0.000100950558f);
    p2 = fmaf(p2, wb, 0.00134934322f);
    p2 = fmaf(p2, wb, -0.00367342844f);
    p2 = fmaf(p2, wb, 0.00573950773f);
    p2 = fmaf(p2, wb, -0.0076224613f);
    p2 = fmaf(p2, wb, 0.00943887047f);
    p2 = fmaf(p2, wb, 1.00167406f);
    p2 = fmaf(p2, wb, 2.83297682f);
    float p = (w < 5.0f) ? p1 : p2;
    return 1.0e-6f * (1.41421353816986084f * (p * u));
}

// --------- FA from symmetric 3x3 (noise pre-reduced to 6 values) ----------
__device__ __forceinline__ float fa_voxel(const float *fit, float n00,
                                          float n11, float n22, float h01,
                                          float h02, float h12, float mind) {
    float a00 = fit[0] + n00;
    float a11 = fit[2] + n11;
    float a22 = fit[5] + n22;
    float a01 = fit[1] + h01;
    float a02 = fit[3] + h02;
    float a12 = fit[4] + h12;

    float q = (a00 + a11 + a22) * (1.0f / 3.0f);
    float m0 = a00 - q, m1 = a11 - q, m2 = a22 - q;
    float off = fmaf(a01, a01, fmaf(a02, a02, a12 * a12));
    float S = fmaf(m0, m0, fmaf(m1, m1, fmaf(m2, m2, 2.0f * off)));
    float fa_fast = __fsqrt_rn(__fdividef(1.5f * S, fmaf(3.0f * q, q, S)));
    float p = __fsqrt_rn(S * (1.0f / 6.0f));
    if (q - 2.0f * p >= mind) return fa_fast;  // lambda_min >= q-2p always

    float det = m0 * fmaf(m1, m2, -a12 * a12)
              - a01 * fmaf(a01, m2, -a12 * a02)
              + a02 * fmaf(a01, a12, -m1 * a02);
    float pinv = __fdividef(1.0f, p);
    float r = 0.5f * det * pinv * pinv * pinv;
    r = fminf(fmaxf(r, -1.0f), 1.0f);  // NaN (p==0) collapses to -1
    float phi = acosf(r) * (1.0f / 3.0f);
    float l3 = fmaf(2.0f * p, __cosf(phi + 2.0943951023931953f), q);  // min
    if (l3 >= mind) return fa_fast;

    float l1 = fmaf(2.0f * p, __cosf(phi), q);  // max
    float l2 = 3.0f * q - l1 - l3;
    l1 = fmaxf(l1, mind);
    l2 = fmaxf(l2, mind);
    l3 = fmaxf(l3, mind);
    float d12 = l1 - l2, d23 = l2 - l3, d31 = l3 - l1;
    float num = 0.5f * fmaf(d12, d12, fmaf(d23, d23, d31 * d31));
    float den = fmaf(l1, l1, fmaf(l2, l2, l3 * l3));
    return __fsqrt_rn(__fdividef(num, den));
}

// ---------------- main kernel ----------------------------------------------
__global__ void __launch_bounds__(TPB, 9)
fa_kernel(const float *__restrict__ dwi, const float *__restrict__ mask,
          const float *__restrict__ Winv, const float *__restrict__ mindp,
          float *__restrict__ out) {
    __shared__ __align__(16) float Wsh[384];
    __shared__ __align__(16) float tile[WARPS_PER_BLK][32 * RS];

    for (int k = threadIdx.x; k < 384; k += TPB)
        Wsh[k] = Winv[k] * 0.6931471805599453f;
    __syncthreads();  // Wsh only; tile is warp-private

    const int warp = threadIdx.x >> 5;
    const int lane = threadIdx.x & 31;
    const unsigned vw = (blockIdx.x * WARPS_PER_BLK + warp) * 32u;
    const unsigned v = vw + (unsigned)lane;

    const float mind = __ldg(mindp);
    const float4 *__restrict__ dwi4 = reinterpret_cast<const float4 *>(dwi);
    float *trow = &tile[warp][0];
    const uint32_t trow_sa =
        (uint32_t)__cvta_generic_to_shared(&tile[warp][0]);

    const unsigned g = lane >> 3u, e = lane & 7u;

    // ---- async-load phase 0 (elems 0..31 of the warp's 32 voxels) ----
#pragma unroll
    for (int k = 0; k < 8; ++k) {
        unsigned gv = min(vw + (unsigned)(k * 4) + g, NVOX - 1u);
        cp_async16(trow_sa + (unsigned)(k * 4 + g) * (RS * 4u) + e * 16u,
                   dwi4 + (size_t)gv * 16u + e);
    }
    cp_commit();

    // ---- noise j=0..4 (ALU hash + FMA erfinv, hides phase-0 latency) ----
    const uint32_t nbase = 9u * v;
    float n00 = noise_from_bits(tf_bits_partitionable(nbase + 0u));
    float n1  = noise_from_bits(tf_bits_partitionable(nbase + 1u));
    float n2  = noise_from_bits(tf_bits_partitionable(nbase + 2u));
    float n3  = noise_from_bits(tf_bits_partitionable(nbase + 3u));
    float n11 = noise_from_bits(tf_bits_partitionable(nbase + 4u));
    float h01 = 0.5f * (n1 + n3);

    cp_wait0();
    __syncwarp();

    // ---- consume phase 0 ----
    u64 acc[6];
#pragma unroll
    for (int i = 0; i < 6; ++i) acc[i] = 0ull;
    const float *myrow = &trow[lane * RS];
#pragma unroll
    for (int jt = 0; jt < 8; ++jt) {
        float4 a = *reinterpret_cast<const float4 *>(&myrow[jt * 4]);
        float l0 = __log2f(fmaxf(a.x, mind));
        float l1 = __log2f(fmaxf(a.y, mind));
        float l2 = __log2f(fmaxf(a.z, mind));
        float l3 = __log2f(fmaxf(a.w, mind));
        u64 l01 = pk2(l0, l1), l23 = pk2(l2, l3);
#pragma unroll
        for (int i = 0; i < 6; ++i) {
            ulonglong2 w =
                *reinterpret_cast<const ulonglong2 *>(&Wsh[i * 64 + jt * 4]);
            acc[i] = fma2(w.x, l01, acc[i]);
            acc[i] = fma2(w.y, l23, acc[i]);
        }
    }
    __syncwarp();  // whole warp done reading phase 0

    // ---- async-load phase 1 into same tile (WAR-safe: LDS long done) ----
#pragma unroll
    for (int k = 0; k < 8; ++k) {
        unsigned gv = min(vw + (unsigned)(k * 4) + g, NVOX - 1u);
        cp_async16(trow_sa + (unsigned)(k * 4 + g) * (RS * 4u) + e * 16u,
                   dwi4 + (size_t)gv * 16u + 8u + e);
    }
    cp_commit();

    // ---- noise j=5..8 (hides phase-1 latency) ----
    float n5  = noise_from_bits(tf_bits_partitionable(nbase + 5u));
    float n6  = noise_from_bits(tf_bits_partitionable(nbase + 6u));
    float n7  = noise_from_bits(tf_bits_partitionable(nbase + 7u));
    float n22 = noise_from_bits(tf_bits_partitionable(nbase + 8u));
    float h02 = 0.5f * (n2 + n6);
    float h12 = 0.5f * (n5 + n7);

    cp_wait0();
    __syncwarp();

    // ---- consume phase 1 ----
#pragma unroll
    for (int jt = 0; jt < 8; ++jt) {
        float4 a = *reinterpret_cast<const float4 *>(&myrow[jt * 4]);
        float l0 = __log2f(fmaxf(a.x, mind));
        float l1 = __log2f(fmaxf(a.y, mind));
        float l2 = __log2f(fmaxf(a.z, mind));
        float l3 = __log2f(fmaxf(a.w, mind));
        u64 l01 = pk2(l0, l1), l23 = pk2(l2, l3);
#pragma unroll
        for (int i = 0; i < 6; ++i) {
            ulonglong2 w = *reinterpret_cast<const ulonglong2 *>(
                &Wsh[i * 64 + 32 + jt * 4]);
            acc[i] = fma2(w.x, l01, acc[i]);
            acc[i] = fma2(w.y, l23, acc[i]);
        }
    }

    float fit[6];
#pragma unroll
    for (int i = 0; i < 6; ++i) {
        float x, y;
        unpk2(acc[i], x, y);
        fit[i] = x + y;
    }

    if (v < NVOX)
        out[v] = fa_voxel(fit, n00, n11, n22, h01, h02, h12, mind) *
                 __ldg(mask + v);
}

extern "C" void kernel_launch(void *const *d_in, const int *in_sizes, int n_in,
                              void *d_out, int out_size) {
    const float *dwi  = (const float *)d_in[0];   // [100,100,100,64]
    const float *mask = (const float *)d_in[1];   // [100,100,100,1]
    const float *winv = (const float *)d_in[2];   // [7,64]
    const float *mind = (const float *)d_in[3];   // scalar
    float *out = (float *)d_out;                  // [100,100,100,1]
    (void)in_sizes; (void)n_in; (void)out_size;

    dim3 grid((NVOX + TPB - 1) / TPB);
    fa_kernel<<<grid, TPB>>>(dwi, mask, winv, mind, out);
}

// round 9
// speedup vs baseline: 1.3076x; 1.0549x over previous
#include <cuda_runtime.h>
#include <stdint.h>

#define TPB 128
#define WARPS_PER_BLK 4
#define NVOX 1000000u
#define RS 36  // smem row stride (floats): conflict-free for both phases

typedef unsigned long long u64;

// ---------------- packed f32x2 helpers (Blackwell) ----------------
__device__ __forceinline__ u64 pk2(float lo, float hi) {
    u64 r;
    asm("mov.b64 %0, {%1, %2};" : "=l"(r) : "f"(lo), "f"(hi));
    return r;
}
__device__ __forceinline__ void unpk2(u64 v, float &lo, float &hi) {
    asm("mov.b64 {%0, %1}, %2;" : "=f"(lo), "=f"(hi) : "l"(v));
}
__device__ __forceinline__ u64 fma2(u64 a, u64 b, u64 c) {
    u64 d;
    asm("fma.rn.f32x2 %0, %1, %2, %3;" : "=l"(d) : "l"(a), "l"(b), "l"(c));
    return d;
}

// ---------------- cp.async 16B ----------------
__device__ __forceinline__ void cp_async16(uint32_t saddr, const void *gptr) {
    asm volatile("cp.async.ca.shared.global [%0], [%1], 16;"
                 :: "r"(saddr), "l"(gptr) : "memory");
}
__device__ __forceinline__ void cp_commit() {
    asm volatile("cp.async.commit_group;" ::: "memory");
}
__device__ __forceinline__ void cp_wait0() {
    asm volatile("cp.async.wait_group 0;" ::: "memory");
}

// ------- threefry2x32, key = jax.random.key(42) -> (k1=0, k2=42) ----------
__device__ __forceinline__ uint32_t tf_bits_partitionable(uint32_t i) {
    uint32_t x0 = 0u, x1 = i;
    const uint32_t ks0 = 0u;
    const uint32_t ks1 = 42u;
    const uint32_t ks2 = 0x1BD11BDAu ^ 0u ^ 42u;
    x0 += ks0; x1 += ks1;
#define TF_R(r) { x0 += x1; x1 = __funnelshift_l(x1, x1, (r)); x1 ^= x0; }
#define TF_G1 TF_R(13) TF_R(15) TF_R(26) TF_R(6)
#define TF_G2 TF_R(17) TF_R(29) TF_R(16) TF_R(24)
    TF_G1 x0 += ks1; x1 += ks2 + 1u;
    TF_G2 x0 += ks2; x1 += ks0 + 2u;
    TF_G1 x0 += ks0; x1 += ks1 + 3u;
    TF_G2 x0 += ks1; x1 += ks2 + 4u;
    TF_G1 x0 += ks2; x1 += ks0 + 5u;
#undef TF_G1
#undef TF_G2
#undef TF_R
    return x0 ^ x1;  // partitionable path: lane0 ^ lane1
}

// bits -> jax.random.normal sample * 1e-6 (SYMEIG_EPS), XLA ErfInv32 exact.
// Big branch (w>=5, P~0.33%/sample) executed only if some lane needs it
// (~10% of sample-warps); per-lane select inside keeps semantics exact.
__device__ __forceinline__ float noise_from_bits(uint32_t bits) {
    const float LO = -0.99999994f;  // nextafter(-1,0); (1-LO) rounds to 2.0f
    float f = __uint_as_float((bits >> 9) | 0x3f800000u) - 1.0f;  // [0,1)
    float u = fmaxf(LO, fmaf(f, 2.0f, LO));
    float z = 1.0f - u * u;  // Sterbenz-exact where log1p accuracy matters
    float w = -0.6931471805599453f * __log2f(z);
    float ws = w - 2.5f;
    float p1 = fmaf(2.81022636e-08f, ws, 3.43273939e-07f);
    p1 = fmaf(p1, ws, -3.5233877e-06f);
    p1 = fmaf(p1, ws, -4.39150654e-06f);
    p1 = fmaf(p1, ws, 0.00021858087f);
    p1 = fmaf(p1, ws, -0.00125372503f);
    p1 = fmaf(p1, ws, -0.00417768164f);
    p1 = fmaf(p1, ws, 0.246640727f);
    p1 = fmaf(p1, ws, 1.50140941f);
    bool big = !(w < 5.0f);
    if (__any_sync(0xffffffffu, big)) {
        float wb = __fsqrt_rn(w) - 3.0f;
        float p2 = fmaf(-0.000200214257f, wb, 0.000100950558f);
        p2 = fmaf(p2, wb, 0.00134934322f);
        p2 = fmaf(p2, wb, -0.00367342844f);
        p2 = fmaf(p2, wb, 0.00573950773f);
        p2 = fmaf(p2, wb, -0.0076224613f);
        p2 = fmaf(p2, wb, 0.00943887047f);
        p2 = fmaf(p2, wb, 1.00167406f);
        p2 = fmaf(p2, wb, 2.83297682f);
        p1 = big ? p2 : p1;
    }
    // 1e-6 * sqrt2_f32 folded into one constant (1 extra ulp on 1e-6 scale)
    return 1.4142135452078743e-06f * (p1 * u);
}

// --------- FA from symmetric 3x3 (noise pre-reduced to 6 values) ----------
__device__ __forceinline__ float fa_voxel(const float *fit, float n00,
                                          float n11, float n22, float h01,
                                          float h02, float h12, float mind) {
    float a00 = fit[0] + n00;
    float a11 = fit[2] + n11;
    float a22 = fit[5] + n22;
    float a01 = fit[1] + h01;
    float a02 = fit[3] + h02;
    float a12 = fit[4] + h12;

    float q = (a00 + a11 + a22) * (1.0f / 3.0f);
    float m0 = a00 - q, m1 = a11 - q, m2 = a22 - q;
    float off = fmaf(a01, a01, fmaf(a02, a02, a12 * a12));
    float S = fmaf(m0, m0, fmaf(m1, m1, fmaf(m2, m2, 2.0f * off)));
    float fa_fast = __fsqrt_rn(__fdividef(1.5f * S, fmaf(3.0f * q, q, S)));
    float p = __fsqrt_rn(S * (1.0f / 6.0f));
    if (q - 2.0f * p >= mind) return fa_fast;  // lambda_min >= q-2p always

    float det = m0 * fmaf(m1, m2, -a12 * a12)
              - a01 * fmaf(a01, m2, -a12 * a02)
              + a02 * fmaf(a01, a12, -m1 * a02);
    float pinv = __fdividef(1.0f, p);
    float r = 0.5f * det * pinv * pinv * pinv;
    r = fminf(fmaxf(r, -1.0f), 1.0f);  // NaN (p==0) collapses to -1
    float phi = acosf(r) * (1.0f / 3.0f);
    float l3 = fmaf(2.0f * p, __cosf(phi + 2.0943951023931953f), q);  // min
    if (l3 >= mind) return fa_fast;

    float l1 = fmaf(2.0f * p, __cosf(phi), q);  // max
    float l2 = 3.0f * q - l1 - l3;
    l1 = fmaxf(l1, mind);
    l2 = fmaxf(l2, mind);
    l3 = fmaxf(l3, mind);
    float d12 = l1 - l2, d23 = l2 - l3, d31 = l3 - l1;
    float num = 0.5f * fmaf(d12, d12, fmaf(d23, d23, d31 * d31));
    float den = fmaf(l1, l1, fmaf(l2, l2, l3 * l3));
    return __fsqrt_rn(__fdividef(num, den));
}

// ---------------- main kernel ----------------------------------------------
__global__ void __launch_bounds__(TPB, 9)
fa_kernel(const float *__restrict__ dwi, const float *__restrict__ mask,
          const float *__restrict__ Winv, const float *__restrict__ mindp,
          float *__restrict__ out) {
    __shared__ __align__(16) float Wsh[384];
    __shared__ __align__(16) float tile[WARPS_PER_BLK][32 * RS];

    for (int k = threadIdx.x; k < 384; k += TPB)
        Wsh[k] = Winv[k] * 0.6931471805599453f;
    __syncthreads();  // Wsh only; tile is warp-private

    const int warp = threadIdx.x >> 5;
    const int lane = threadIdx.x & 31;
    const unsigned vw = (blockIdx.x * WARPS_PER_BLK + warp) * 32u;
    const unsigned v = vw + (unsigned)lane;
    const bool full = (vw + 32u <= NVOX);  // warp-uniform

    const float mind = __ldg(mindp);
    const float4 *__restrict__ dwi4 = reinterpret_cast<const float4 *>(dwi);
    float *trow = &tile[warp][0];
    const uint32_t trow_sa =
        (uint32_t)__cvta_generic_to_shared(&tile[warp][0]);

    const unsigned g = lane >> 3u, e = lane & 7u;
    // lane's smem base: voxel row (g) + 16B chunk (e)
    const uint32_t sa = trow_sa + g * (RS * 4u) + e * 16u;

    // ---- async-load phase 0 (elems 0..31 of the warp's 32 voxels) ----
    if (full) {
#pragma unroll
        for (int k = 0; k < 8; ++k)
            cp_async16(sa + (unsigned)(k * 4) * (RS * 4u),
                       dwi4 + (size_t)(vw + (unsigned)(k * 4) + g) * 16u + e);
    } else {
#pragma unroll
        for (int k = 0; k < 8; ++k) {
            unsigned gv = min(vw + (unsigned)(k * 4) + g, NVOX - 1u);
            cp_async16(sa + (unsigned)(k * 4) * (RS * 4u),
                       dwi4 + (size_t)gv * 16u + e);
        }
    }
    cp_commit();

    // ---- noise j=0..4 (hides phase-0 latency) ----
    const uint32_t nbase = 9u * v;
    float n00 = noise_from_bits(tf_bits_partitionable(nbase + 0u));
    float n1  = noise_from_bits(tf_bits_partitionable(nbase + 1u));
    float n2  = noise_from_bits(tf_bits_partitionable(nbase + 2u));
    float n3  = noise_from_bits(tf_bits_partitionable(nbase + 3u));
    float n11 = noise_from_bits(tf_bits_partitionable(nbase + 4u));
    float h01 = 0.5f * (n1 + n3);

    cp_wait0();
    __syncwarp();

    // ---- consume phase 0 ----
    u64 acc[6];
#pragma unroll
    for (int i = 0; i < 6; ++i) acc[i] = 0ull;
    const float *myrow = &trow[lane * RS];
#pragma unroll
    for (int jt = 0; jt < 8; ++jt) {
        float4 a = *reinterpret_cast<const float4 *>(&myrow[jt * 4]);
        float l0 = __log2f(fmaxf(a.x, mind));
        float l1 = __log2f(fmaxf(a.y, mind));
        float l2 = __log2f(fmaxf(a.z, mind));
        float l3 = __log2f(fmaxf(a.w, mind));
        u64 l01 = pk2(l0, l1), l23 = pk2(l2, l3);
#pragma unroll
        for (int i = 0; i < 6; ++i) {
            ulonglong2 w =
                *reinterpret_cast<const ulonglong2 *>(&Wsh[i * 64 + jt * 4]);
            acc[i] = fma2(w.x, l01, acc[i]);
            acc[i] = fma2(w.y, l23, acc[i]);
        }
    }
    __syncwarp();  // whole warp done reading phase 0

    // ---- async-load phase 1 into same tile (WAR-safe: LDS long done) ----
    if (full) {
#pragma unroll
        for (int k = 0; k < 8; ++k)
            cp_async16(sa + (unsigned)(k * 4) * (RS * 4u),
                       dwi4 + (size_t)(vw + (unsigned)(k * 4) + g) * 16u + 8u +
                           e);
    } else {
#pragma unroll
        for (int k = 0; k < 8; ++k) {
            unsigned gv = min(vw + (unsigned)(k * 4) + g, NVOX - 1u);
            cp_async16(sa + (unsigned)(k * 4) * (RS * 4u),
                       dwi4 + (size_t)gv * 16u + 8u + e);
        }
    }
    cp_commit();

    // prefetch mask early (hides LDG latency behind noise j=5..8)
    const float mval = __ldg(mask + min(v, NVOX - 1u));

    // ---- noise j=5..8 (hides phase-1 latency) ----
    float n5  = noise_from_bits(tf_bits_partitionable(nbase + 5u));
    float n6  = noise_from_bits(tf_bits_partitionable(nbase + 6u));
    float n7  = noise_from_bits(tf_bits_partitionable(nbase + 7u));
    float n22 = noise_from_bits(tf_bits_partitionable(nbase + 8u));
    float h02 = 0.5f * (n2 + n6);
    float h12 = 0.5f * (n5 + n7);

    cp_wait0();
    __syncwarp();

    // ---- consume phase 1 ----
#pragma unroll
    for (int jt = 0; jt < 8; ++jt) {
        float4 a = *reinterpret_cast<const float4 *>(&myrow[jt * 4]);
        float l0 = __log2f(fmaxf(a.x, mind));
        float l1 = __log2f(fmaxf(a.y, mind));
        float l2 = __log2f(fmaxf(a.z, mind));
        float l3 = __log2f(fmaxf(a.w, mind));
        u64 l01 = pk2(l0, l1), l23 = pk2(l2, l3);
#pragma unroll
        for (int i = 0; i < 6; ++i) {
            ulonglong2 w = *reinterpret_cast<const ulonglong2 *>(
                &Wsh[i * 64 + 32 + jt * 4]);
            acc[i] = fma2(w.x, l01, acc[i]);
            acc[i] = fma2(w.y, l23, acc[i]);
        }
    }

    float fit[6];
#pragma unroll
    for (int i = 0; i < 6; ++i) {
        float x, y;
        unpk2(acc[i], x, y);
        fit[i] = x + y;
    }

    if (v < NVOX)
        out[v] = fa_voxel(fit, n00, n11, n22, h01, h02, h12, mind) * mval;
}

extern "C" void kernel_launch(void *const *d_in, const int *in_sizes, int n_in,
                              void *d_out, int out_size) {
    const float *dwi  = (const float *)d_in[0];   // [100,100,100,64]
    const float *mask = (const float *)d_in[1];   // [100,100,100,1]
    const float *winv = (const float *)d_in[2];   // [7,64]
    const float *mind = (const float *)d_in[3];   // scalar
    float *out = (float *)d_out;                  // [100,100,100,1]
    (void)in_sizes; (void)n_in; (void)out_size;

    dim3 grid((NVOX + TPB - 1) / TPB);
    fa_kernel<<<grid, TPB>>>(dwi, mask, winv, mind, out);
}